// round 3
// baseline (speedup 1.0000x reference)
#include <cuda_runtime.h>

// Hopf oscillator CPG step, reformulated:
//   sin(psi_j - psi_i - phi_ij) = (s_j c_i - c_j s_i)cos(phi) - (c_j c_i + s_j s_i)sin(phi)
// A_ij = w_zd*cos(phi_zd), B_ij = w_zd*sin(phi_zd), x_j = r_j s_j, y_j = r_j c_j:
//   coupling_i = c_i*(A x - B y)_i - s_i*(A y + B x)_i
// Matrix row i lives in REGISTERS (float2 ab[32], prefetched conflict-free from smem).
// Packed f32x2 FMAs pair two batch rows; xy broadcasts load as ulonglong2 (no packs).

#define PI2F 6.28318530717958647692f

typedef unsigned long long u64;

__device__ __forceinline__ u64 pack2(float lo, float hi) {
    u64 r;
    asm("mov.b64 %0, {%1, %2};" : "=l"(r) : "f"(lo), "f"(hi));
    return r;
}
__device__ __forceinline__ void unpack2(u64 v, float& lo, float& hi) {
    asm("mov.b64 {%0, %1}, %2;" : "=f"(lo), "=f"(hi) : "l"(v));
}
#define FMA2(acc, a, b) asm("fma.rn.f32x2 %0, %1, %2, %0;" : "+l"(acc) : "l"(a), "l"(b))

__device__ __forceinline__ float fsigmoid(float x) {
    return 1.0f / (1.0f + __expf(-x));
}

__global__ __launch_bounds__(256, 2)
void hopf_kernel(const float* __restrict__ in, float* __restrict__ out,
                 const float* __restrict__ v, const float* __restrict__ b,
                 const float* __restrict__ c, const float* __restrict__ w,
                 const float* __restrict__ phi, int nrows) {
    const int tid  = threadIdx.x;
    const int lane = tid & 31;          // oscillator index i
    const int wib  = tid >> 5;          // warp in block (0..7)
    const int gw   = blockIdx.x * 8 + wib;

    // sAB[j*32 + i] = {A[i][j], B[i][j]}  -> lane-consecutive LDS.64, conflict-free
    __shared__ float2 sAB[1024];
    __shared__ float4 sXY[8][2][32];    // per-warp {x0,x1,y0,y1} broadcast buffers

    // ---- build activation matrix in smem (4 entries per thread) ----
    #pragma unroll
    for (int k = 0; k < 4; k++) {
        int m = tid + k * 256;          // flat index, i = m/32, j = m%32
        float A = 0.0f, Bv = 0.0f;
        if (m % 33 != 0) {              // zero-diag: diagonal iff m % 33 == 0
            int kk = m / 33;            // 0..30
            int jj = m % 33 - 1;        // 0..31
            float wa = fsigmoid(w[kk * 32 + jj]);           // W_MAX = 1
            float pa = PI2F * fsigmoid(phi[kk * 32 + jj]);  // PHI_MAX = 2*pi
            float sp, cp;
            __sincosf(pa, &sp, &cp);
            A  = wa * cp;
            Bv = wa * sp;
        }
        sAB[(m & 31) * 32 + (m >> 5)] = make_float2(A, Bv);  // store [j][i]
    }

    // per-lane activations
    const float tpv = (PI2F * 5.0f) * fsigmoid(v[lane]);
    const float ba  = 2.0f  * fsigmoid(b[lane]);
    const float ca  = 10.0f * fsigmoid(c[lane]);

    __syncthreads();

    // ---- prefetch matrix row i into registers (conflict-free LDS.64) ----
    float2 ab[32];
    #pragma unroll
    for (int j = 0; j < 32; j++) ab[j] = sAB[j * 32 + lane];

    const int rowBase = gw * 16;        // 16 rows per warp, four 4-row quads

    #pragma unroll
    for (int q = 0; q < 4; q++) {
        const int r0 = rowBase + q * 4;
        float sv[4], cv[4], xv[4], yv[4];

        #pragma unroll
        for (int t = 0; t < 4; t++) {
            const int row = r0 + t;
            float psi = 0.0f, rr = 0.0f, rd = 0.0f;
            if (row < nrows) {
                const float* rp = in + (size_t)row * 96;
                psi = rp[lane];
                rr  = rp[32 + lane];
                rd  = rp[64 + lane];
            }
            __sincosf(psi, &sv[t], &cv[t]);
            xv[t] = rr * sv[t];
            yv[t] = rr * cv[t];
            if (row < nrows) {
                float rdd = ca * (0.25f * ca * (ba - rr) - rd);
                float* op = out + (size_t)row * 96;
                op[32 + lane] = rd;
                op[64 + lane] = rdd;
            }
        }

        __syncwarp();   // previous quad's readers done before overwrite
        sXY[wib][0][lane] = make_float4(xv[0], xv[1], yv[0], yv[1]);
        sXY[wib][1][lane] = make_float4(xv[2], xv[3], yv[2], yv[3]);
        __syncwarp();

        // accumulators: P1=sum(Ax), P2=sum(By), Q1=sum(Ay), Q2=sum(Bx)
        u64 aP1 = 0, aP2 = 0, aQ1 = 0, aQ2 = 0;   // rows (0,1)
        u64 bP1 = 0, bP2 = 0, bQ1 = 0, bQ2 = 0;   // rows (2,3)

        #pragma unroll
        for (int j = 0; j < 32; j++) {
            u64 AA = pack2(ab[j].x, ab[j].x);      // {A,A} (2 ALU movs)
            u64 BB = pack2(ab[j].y, ab[j].y);      // {B,B}
            // {X0,Y0} and {X1,Y1} directly as u64 pairs (broadcast LDS.128)
            ulonglong2 p0 = *reinterpret_cast<const ulonglong2*>(&sXY[wib][0][j]);
            ulonglong2 p1 = *reinterpret_cast<const ulonglong2*>(&sXY[wib][1][j]);
            FMA2(aP1, AA, p0.x);  FMA2(aP2, BB, p0.y);
            FMA2(aQ1, AA, p0.y);  FMA2(aQ2, BB, p0.x);
            FMA2(bP1, AA, p1.x);  FMA2(bP2, BB, p1.y);
            FMA2(bQ1, AA, p1.y);  FMA2(bQ2, BB, p1.x);
        }

        float P[4], Q[4];
        {
            float l0,h0,l1,h1,l2,h2,l3,h3;
            unpack2(aP1,l0,h0); unpack2(aP2,l1,h1);
            unpack2(aQ1,l2,h2); unpack2(aQ2,l3,h3);
            P[0] = l0 - l1;  P[1] = h0 - h1;
            Q[0] = l2 + l3;  Q[1] = h2 + h3;
        }
        {
            float l0,h0,l1,h1,l2,h2,l3,h3;
            unpack2(bP1,l0,h0); unpack2(bP2,l1,h1);
            unpack2(bQ1,l2,h2); unpack2(bQ2,l3,h3);
            P[2] = l0 - l1;  P[3] = h0 - h1;
            Q[2] = l2 + l3;  Q[3] = h2 + h3;
        }

        #pragma unroll
        for (int t = 0; t < 4; t++) {
            const int row = r0 + t;
            if (row < nrows) {
                float psi_dot = tpv + cv[t] * P[t] - sv[t] * Q[t];
                out[(size_t)row * 96 + lane] = psi_dot;
            }
        }
    }
}

extern "C" void kernel_launch(void* const* d_in, const int* in_sizes, int n_in,
                              void* d_out, int out_size) {
    const float* states = (const float*)d_in[0];
    const float* v      = (const float*)d_in[1];
    const float* b      = (const float*)d_in[2];
    const float* c      = (const float*)d_in[3];
    const float* w      = (const float*)d_in[4];
    const float* phi    = (const float*)d_in[5];
    float* out = (float*)d_out;

    const int nrows = in_sizes[0] / 96;     // 65536
    const int rows_per_warp = 16;
    const int warps  = (nrows + rows_per_warp - 1) / rows_per_warp;
    const int blocks = (warps + 7) / 8;     // 8 warps (256 threads) per block

    hopf_kernel<<<blocks, 256>>>(states, out, v, b, c, w, phi, nrows);
}